// round 1
// baseline (speedup 1.0000x reference)
#include <cuda_runtime.h>
#include <math.h>

// Problem constants
#define BB   16
#define CC   256
#define OO   256
#define HH   32
#define WW   32
#define EE   4
#define CR   16
#define GG   8
#define CPG  32          // channels per group (OO/GG)
#define HWSZ 1024        // HH*WW
#define EPSV 1e-5f

// ---------------- scratch (device globals; no allocation allowed) -----------
__device__ float g_pooled[BB * CC];
__device__ float g_gate[BB * EE];
__device__ float g_shared_raw[BB * OO * HWSZ];                 // 16.8 MB
__device__ float g_expert_raw[(size_t)BB * EE * OO * HWSZ];    // 67 MB
__device__ float g_sh_mean[BB * GG], g_sh_rstd[BB * GG];
__device__ float g_ex_mean[BB * EE * GG], g_ex_rstd[BB * EE * GG];

__device__ __forceinline__ float warpsum(float v) {
    #pragma unroll
    for (int o = 16; o > 0; o >>= 1) v += __shfl_down_sync(0xffffffffu, v, o);
    return v;
}

__device__ __forceinline__ float silu(float v) {
    return v / (1.0f + expf(-v));
}

// ---------------- K1a: global average pool ----------------------------------
// grid = BB*CC/8 = 512 blocks x 256 threads; one warp per (b,c)
__global__ void pool_kernel(const float* __restrict__ x) {
    int warp = threadIdx.x >> 5, lane = threadIdx.x & 31;
    int idx = blockIdx.x * 8 + warp;           // b*CC + c
    const float* p = x + (size_t)idx * HWSZ;
    float s = 0.f;
    for (int i = lane; i < HWSZ; i += 32) s += p[i];
    s = warpsum(s);
    if (lane == 0) g_pooled[idx] = s * (1.0f / HWSZ);
}

// ---------------- K1b: router MLP + softmax + top-2 gate --------------------
// single block, 256 threads
__global__ void router_kernel(const float* __restrict__ w1, const float* __restrict__ b1,
                              const float* __restrict__ w2, const float* __restrict__ b2) {
    __shared__ float hs[BB][CR];
    __shared__ float lg[BB][EE];
    int tid = threadIdx.x;
    {
        int b = tid / CR, j = tid % CR;       // 16*16 = 256 threads, all used
        float s = b1[j];
        const float* wr = w1 + j * CC;
        const float* pr = g_pooled + b * CC;
        for (int c = 0; c < CC; c++) s = fmaf(wr[c], pr[c], s);
        hs[b][j] = silu(s);
    }
    __syncthreads();
    if (tid < BB * EE) {
        int b = tid / EE, e = tid % EE;
        float s = b2[e];
        for (int j = 0; j < CR; j++) s = fmaf(w2[e * CR + j], hs[b][j], s);
        lg[b][e] = s;                          // TEMPERATURE == 1
    }
    __syncthreads();
    if (tid < BB) {
        int b = tid;
        float m = lg[b][0];
        for (int e = 1; e < EE; e++) m = fmaxf(m, lg[b][e]);
        float p[EE]; float Z = 0.f;
        for (int e = 0; e < EE; e++) { p[e] = expf(lg[b][e] - m); Z += p[e]; }
        for (int e = 0; e < EE; e++) p[e] /= Z;
        // top-2 (first occurrence wins ties, matching lax.top_k)
        int i1 = 0;
        for (int e = 1; e < EE; e++) if (p[e] > p[i1]) i1 = e;
        int i2 = -1;
        for (int e = 0; e < EE; e++) {
            if (e == i1) continue;
            if (i2 < 0 || p[e] > p[i2]) i2 = e;
        }
        float v1 = p[i1], v2 = p[i2], sum = v1 + v2;
        float wA = v1 / sum, wB = v2 / sum;
        if (wA < 0.01f) wA = 0.f;
        if (wB < 0.01f) wB = 0.f;
        for (int e = 0; e < EE; e++) g_gate[b * EE + e] = 0.f;
        g_gate[b * EE + i1] = wA;
        g_gate[b * EE + i2] = wB;
    }
}

// ---------------- K2: shared 1x1 conv (GEMM) --------------------------------
// grid (8 px-tiles, 4 o-tiles, BB); 256 threads; each warp: 8 o x 128 px
__global__ void shared_conv_kernel(const float* __restrict__ x,
                                   const float* __restrict__ sw) {
    int b = blockIdx.z, o0 = blockIdx.y * 64, p0 = blockIdx.x * 128;
    int warp = threadIdx.x >> 5, lane = threadIdx.x & 31;
    __shared__ float xs[16][128];
    __shared__ float ws[64][16];
    float acc[8][4];
    #pragma unroll
    for (int i = 0; i < 8; i++)
        #pragma unroll
        for (int k = 0; k < 4; k++) acc[i][k] = 0.f;

    const float* xb = x + (size_t)b * CC * HWSZ;
    for (int c0 = 0; c0 < CC; c0 += 16) {
        for (int i = threadIdx.x; i < 16 * 128; i += 256) {
            int cc = i >> 7, p = i & 127;
            xs[cc][p] = xb[(size_t)(c0 + cc) * HWSZ + p0 + p];
        }
        for (int i = threadIdx.x; i < 64 * 16; i += 256) {
            int oi = i >> 4, cc = i & 15;
            ws[oi][cc] = sw[(size_t)(o0 + oi) * CC + c0 + cc];
        }
        __syncthreads();
        #pragma unroll
        for (int cc = 0; cc < 16; cc++) {
            float xv[4];
            #pragma unroll
            for (int k = 0; k < 4; k++) xv[k] = xs[cc][lane + 32 * k];
            #pragma unroll
            for (int i = 0; i < 8; i++) {
                float wv = ws[warp * 8 + i][cc];
                #pragma unroll
                for (int k = 0; k < 4; k++) acc[i][k] = fmaf(wv, xv[k], acc[i][k]);
            }
        }
        __syncthreads();
    }
    float* outp = g_shared_raw + (size_t)b * OO * HWSZ;
    #pragma unroll
    for (int i = 0; i < 8; i++) {
        int o = o0 + warp * 8 + i;
        #pragma unroll
        for (int k = 0; k < 4; k++)
            outp[(size_t)o * HWSZ + p0 + lane + 32 * k] = acc[i][k];
    }
}

// ---------------- K3: expert 3x3 conv (gated, direct) -----------------------
// grid (8 row-tiles, 4 o-tiles, BB*EE); 256 threads
// warp -> 8 output channels; lane -> column; 4 rows per thread => 32 accs
__global__ void expert_conv_kernel(const float* __restrict__ x,
                                   const float* __restrict__ ew) {
    int be = blockIdx.z;
    int b = be >> 2, e = be & 3;
    if (g_gate[b * EE + e] == 0.f) return;     // conditional compute
    int o0 = blockIdx.y * 64, h0 = blockIdx.x * 4;
    int warp = threadIdx.x >> 5, lane = threadIdx.x & 31;

    const int KC = 8;
    __shared__ float xs[KC][6][34];            // rows h0-1..h0+4, cols -1..32
    __shared__ float ws[64][KC * 9];

    float acc[8][4];
    #pragma unroll
    for (int i = 0; i < 8; i++)
        #pragma unroll
        for (int k = 0; k < 4; k++) acc[i][k] = 0.f;

    const float* xb = x + (size_t)b * CC * HWSZ;
    const float* wb = ew + (size_t)e * OO * CC * 9;

    for (int c0 = 0; c0 < CC; c0 += KC) {
        // x tile with halo + zero padding
        for (int i = threadIdx.x; i < KC * 6 * 34; i += 256) {
            int cc = i / (6 * 34);
            int rem = i % (6 * 34);
            int rr = rem / 34, cl = rem % 34;
            int gh = h0 - 1 + rr, gw = cl - 1;
            float v = 0.f;
            if (gh >= 0 && gh < HH && gw >= 0 && gw < WW)
                v = xb[(size_t)(c0 + cc) * HWSZ + gh * WW + gw];
            xs[cc][rr][cl] = v;
        }
        // weight tile: contiguous 72-float runs per output channel
        for (int i = threadIdx.x; i < 64 * KC * 9; i += 256) {
            int oi = i / (KC * 9);
            int rem = i % (KC * 9);
            ws[oi][rem] = wb[(size_t)(o0 + oi) * CC * 9 + (size_t)c0 * 9 + rem];
        }
        __syncthreads();

        for (int cc = 0; cc < KC; cc++) {
            #pragma unroll
            for (int r = 0; r < 3; r++) {
                #pragma unroll
                for (int s = 0; s < 3; s++) {
                    float xv[4];
                    #pragma unroll
                    for (int row = 0; row < 4; row++)
                        xv[row] = xs[cc][row + r][lane + s];
                    #pragma unroll
                    for (int i = 0; i < 8; i++) {
                        float wv = ws[warp * 8 + i][cc * 9 + r * 3 + s];
                        #pragma unroll
                        for (int row = 0; row < 4; row++)
                            acc[i][row] = fmaf(wv, xv[row], acc[i][row]);
                    }
                }
            }
        }
        __syncthreads();
    }

    float* outp = g_expert_raw + (size_t)(b * EE + e) * OO * HWSZ;
    #pragma unroll
    for (int i = 0; i < 8; i++) {
        int o = o0 + warp * 8 + i;
        #pragma unroll
        for (int row = 0; row < 4; row++)
            outp[(size_t)o * HWSZ + (h0 + row) * WW + lane] = acc[i][row];
    }
}

// ---------------- K4: GroupNorm statistics ----------------------------------
// blocks [0, BB*GG): shared;  [BB*GG, BB*GG + BB*EE*GG): experts (gated)
__global__ void stats_kernel() {
    int bid = blockIdx.x;
    const float* src;
    float *mout, *rout;
    int idx;
    if (bid < BB * GG) {
        int b = bid / GG, g = bid % GG;
        src = g_shared_raw + ((size_t)b * OO + g * CPG) * HWSZ;
        mout = g_sh_mean; rout = g_sh_rstd; idx = bid;
    } else {
        int t = bid - BB * GG;                 // b*EE*GG + e*GG + g
        int beg = t / GG;                      // b*EE + e
        int g = t % GG;
        if (g_gate[beg] == 0.f) return;
        src = g_expert_raw + ((size_t)beg * OO + g * CPG) * HWSZ;
        mout = g_ex_mean; rout = g_ex_rstd; idx = t;
    }
    float s = 0.f, sq = 0.f;
    for (int i = threadIdx.x; i < CPG * HWSZ; i += 256) {
        float v = src[i];
        s += v;
        sq = fmaf(v, v, sq);
    }
    s = warpsum(s); sq = warpsum(sq);
    __shared__ float ss[8], sqs[8];
    int warp = threadIdx.x >> 5, lane = threadIdx.x & 31;
    if (lane == 0) { ss[warp] = s; sqs[warp] = sq; }
    __syncthreads();
    if (threadIdx.x == 0) {
        float S = 0.f, Q = 0.f;
        #pragma unroll
        for (int i = 0; i < 8; i++) { S += ss[i]; Q += sqs[i]; }
        const float inv = 1.0f / (CPG * HWSZ);
        float mean = S * inv;
        float var = Q * inv - mean * mean;
        mout[idx] = mean;
        rout[idx] = rsqrtf(var + EPSV);
    }
}

// ---------------- K5: normalize + SiLU + gated combine ----------------------
__global__ void combine_kernel(const float* __restrict__ egam, const float* __restrict__ ebet,
                               const float* __restrict__ sgam, const float* __restrict__ sbet,
                               float* __restrict__ out) {
    size_t i = (size_t)blockIdx.x * 256 + threadIdx.x;  // over BB*OO*HWSZ
    int hw = (int)(i & 1023);
    size_t t = i >> 10;
    int o = (int)(t & 255);
    int b = (int)(t >> 8);
    int g = o >> 5;

    float v = g_shared_raw[i];
    float m = g_sh_mean[b * GG + g], r = g_sh_rstd[b * GG + g];
    float vn = fmaf((v - m) * r, sgam[o], sbet[o]);
    float res = silu(vn);

    #pragma unroll
    for (int e = 0; e < EE; e++) {
        float ge = g_gate[b * EE + e];
        if (ge != 0.f) {
            int beg = b * EE + e;
            size_t ei = (((size_t)beg * OO + o) << 10) + hw;
            float ev = g_expert_raw[ei];
            float em = g_ex_mean[beg * GG + g], er = g_ex_rstd[beg * GG + g];
            float en = fmaf((ev - em) * er, egam[e * OO + o], ebet[e * OO + o]);
            res = fmaf(ge, silu(en), res);
        }
    }
    out[i] = res;
}

// ---------------- launch ----------------------------------------------------
extern "C" void kernel_launch(void* const* d_in, const int* in_sizes, int n_in,
                              void* d_out, int out_size) {
    const float* x    = (const float*)d_in[0];
    const float* rw1  = (const float*)d_in[1];
    const float* rb1  = (const float*)d_in[2];
    const float* rw2  = (const float*)d_in[3];
    const float* rb2  = (const float*)d_in[4];
    const float* ew   = (const float*)d_in[5];
    const float* egam = (const float*)d_in[6];
    const float* ebet = (const float*)d_in[7];
    const float* sw   = (const float*)d_in[8];
    const float* sgam = (const float*)d_in[9];
    const float* sbet = (const float*)d_in[10];
    float* out = (float*)d_out;

    pool_kernel<<<BB * CC / 8, 256>>>(x);
    router_kernel<<<1, 256>>>(rw1, rb1, rw2, rb2);
    shared_conv_kernel<<<dim3(8, 4, BB), 256>>>(x, sw);
    expert_conv_kernel<<<dim3(8, 4, BB * EE), 256>>>(x, ew);
    stats_kernel<<<BB * GG + BB * EE * GG, 256>>>();
    combine_kernel<<<(BB * OO * HWSZ) / 256, 256>>>(egam, ebet, sgam, sbet, out);
}

// round 5
// speedup vs baseline: 2.7040x; 2.7040x over previous
#include <cuda_runtime.h>
#include <math.h>

// Problem constants
#define BB   16
#define CC   256
#define OO   256
#define HH   32
#define WW   32
#define EE   4
#define CR   16
#define GG   8
#define CPG  32
#define HWSZ 1024
#define EPSV 1e-5f

#define PADW 34
#define PADPX (PADW * PADW)
#define KTOT (CC * 9)              // 2304
#define NSTG 3
#define TILE_BYTES 16384           // 128 rows x 32 floats
#define STAGE_BYTES (2 * TILE_BYTES)
#define SMEM_TOTAL (NSTG * STAGE_BYTES)   // 98304

// ---------------- scratch ----------------------------------------------------
__device__ float g_pooled[BB * CC];
__device__ float g_gate[BB * EE];
__device__ float g_xT[(size_t)BB * PADPX * CC];              // padded px-major, k-permuted, tf32
__device__ float g_wT[(size_t)EE * 9 * OO * CC];             // [e][rs][o][c_perm], tf32
__device__ float g_swT[OO * CC];                             // shared 1x1 weights, permuted tf32
__device__ float g_shared_raw[(size_t)BB * OO * HWSZ];
__device__ float g_expert_raw[(size_t)BB * EE * OO * HWSZ];
__device__ float g_sh_mean[BB * GG], g_sh_rstd[BB * GG];
__device__ float g_ex_mean[BB * EE * GG], g_ex_rstd[BB * EE * GG];

// ---------------- helpers ----------------------------------------------------
__device__ __forceinline__ float warpsum(float v) {
    #pragma unroll
    for (int o = 16; o > 0; o >>= 1) v += __shfl_down_sync(0xffffffffu, v, o);
    return v;
}
__device__ __forceinline__ float silu(float v) { return v / (1.0f + expf(-v)); }

__device__ __forceinline__ float to_tf32(float x) {
    unsigned r;
    asm("cvt.rna.tf32.f32 %0, %1;" : "=r"(r) : "f"(x));
    return __uint_as_float(r);
}
// permute k within 8-groups so fragment pairs (k, k+4) are adjacent
__device__ __forceinline__ int kperm(int c) {
    return (c & ~7) | ((c & 3) << 1) | ((c & 4) >> 2);
}

__device__ __forceinline__ unsigned smem_u32(const void* p) {
    unsigned a;
    asm("{ .reg .u64 t; cvta.to.shared.u64 t, %1; cvt.u32.u64 %0, t; }" : "=r"(a) : "l"(p));
    return a;
}
__device__ __forceinline__ void cp16(unsigned dst, const float* src) {
    asm volatile("cp.async.cg.shared.global [%0], [%1], 16;" :: "r"(dst), "l"(src));
}
__device__ __forceinline__ void cp_commit() { asm volatile("cp.async.commit_group;"); }

__device__ __forceinline__ void mma_tf32(float* c, unsigned a0, unsigned a1, unsigned a2, unsigned a3,
                                         unsigned b0, unsigned b1) {
    asm volatile(
        "mma.sync.aligned.m16n8k8.row.col.f32.tf32.tf32.f32 "
        "{%0,%1,%2,%3}, {%4,%5,%6,%7}, {%8,%9}, {%0,%1,%2,%3};"
        : "+f"(c[0]), "+f"(c[1]), "+f"(c[2]), "+f"(c[3])
        : "r"(a0), "r"(a1), "r"(a2), "r"(a3), "r"(b0), "r"(b1));
}

// ---------------- K1a: global average pool -----------------------------------
__global__ void pool_kernel(const float* __restrict__ x) {
    int warp = threadIdx.x >> 5, lane = threadIdx.x & 31;
    int idx = blockIdx.x * 8 + warp;
    const float* p = x + (size_t)idx * HWSZ;
    float s = 0.f;
    for (int i = lane; i < HWSZ; i += 32) s += p[i];
    s = warpsum(s);
    if (lane == 0) g_pooled[idx] = s * (1.0f / HWSZ);
}

// ---------------- K1b: router ------------------------------------------------
__global__ void router_kernel(const float* __restrict__ w1, const float* __restrict__ b1,
                              const float* __restrict__ w2, const float* __restrict__ b2) {
    __shared__ float hs[BB][CR];
    __shared__ float lg[BB][EE];
    int tid = threadIdx.x;
    {
        int b = tid / CR, j = tid % CR;
        float s = b1[j];
        const float* wr = w1 + j * CC;
        const float* pr = g_pooled + b * CC;
        for (int c = 0; c < CC; c++) s = fmaf(wr[c], pr[c], s);
        hs[b][j] = silu(s);
    }
    __syncthreads();
    if (tid < BB * EE) {
        int b = tid / EE, e = tid % EE;
        float s = b2[e];
        for (int j = 0; j < CR; j++) s = fmaf(w2[e * CR + j], hs[b][j], s);
        lg[b][e] = s;
    }
    __syncthreads();
    if (tid < BB) {
        int b = tid;
        float m = lg[b][0];
        for (int e = 1; e < EE; e++) m = fmaxf(m, lg[b][e]);
        float p[EE]; float Z = 0.f;
        for (int e = 0; e < EE; e++) { p[e] = expf(lg[b][e] - m); Z += p[e]; }
        for (int e = 0; e < EE; e++) p[e] /= Z;
        int i1 = 0;
        for (int e = 1; e < EE; e++) if (p[e] > p[i1]) i1 = e;
        int i2 = -1;
        for (int e = 0; e < EE; e++) {
            if (e == i1) continue;
            if (i2 < 0 || p[e] > p[i2]) i2 = e;
        }
        float v1 = p[i1], v2 = p[i2], sum = v1 + v2;
        float wA = v1 / sum, wB = v2 / sum;
        if (wA < 0.01f) wA = 0.f;
        if (wB < 0.01f) wB = 0.f;
        for (int e = 0; e < EE; e++) g_gate[b * EE + e] = 0.f;
        g_gate[b * EE + i1] = wA;
        g_gate[b * EE + i2] = wB;
    }
}

// ---------------- K2a: x -> padded px-major, k-permuted, tf32 -----------------
__global__ void xt_kernel(const float* __restrict__ x) {
    int b = blockIdx.y;
    int hp = blockIdx.x;
    int h = hp - 1;
    float* outrow = g_xT + ((size_t)b * PADPX + (size_t)hp * PADW) * CC;
    int tid = threadIdx.x;
    if (h < 0 || h >= HH) {
        for (int i = tid; i < PADW * CC; i += 256) outrow[i] = 0.f;
        return;
    }
    outrow[tid] = 0.f;
    outrow[33 * CC + tid] = 0.f;
    __shared__ float s[CC][33];
    // stage ALL 256 channels x 32 cols of this image row (fix: full coverage)
    for (int i = tid; i < CC * WW; i += 256) {
        int c = i >> 5, w = i & 31;
        s[c][w] = x[((size_t)(b * CC + c)) * HWSZ + h * WW + w];
    }
    __syncthreads();
    for (int i = tid; i < WW * CC; i += 256) {
        int w = i >> 8, c = i & 255;
        outrow[(size_t)(w + 1) * CC + kperm(c)] = to_tf32(s[c][w]);
    }
}

// ---------------- K2b: expert weights -> [e][rs][o][c_perm], tf32 -------------
__global__ void wrepack_kernel(const float* __restrict__ ew) {
    int idx = blockIdx.x * 256 + threadIdx.x;      // e*65536 + o*256 + c
    int c = idx & 255, o = (idx >> 8) & 255, e = idx >> 16;
    const float* src = ew + (size_t)idx * 9;
    int cp = kperm(c);
    #pragma unroll
    for (int j = 0; j < 9; j++)
        g_wT[(((size_t)(e * 9 + j) * OO + o) << 8) + cp] = to_tf32(src[j]);
}

// ---------------- K2c: shared weights -> permuted tf32 ------------------------
__global__ void swt_kernel(const float* __restrict__ sw) {
    int idx = blockIdx.x * 256 + threadIdx.x;      // o*256 + c
    int c = idx & 255, o = idx >> 8;
    g_swT[(o << 8) + kperm(c)] = to_tf32(sw[idx]);
}

// ---------------- K3: unified tf32 warp-MMA GEMM ------------------------------
// grid (8 px-tiles, 2 o-tiles, 80); 256 threads.
// CTA tile 128px x 128o; warp grid 2(M) x 4(N); warp tile 64x32 (m16n8k8).
__global__ void __launch_bounds__(256)
gemm_kernel() {
    extern __shared__ char smem[];
    unsigned sb = smem_u32(smem);
    int tid = threadIdx.x, warp = tid >> 5, lane = tid & 31;
    int warp_m = warp >> 2, warp_n = warp & 3;
    int g = lane >> 2, q = lane & 3;

    int z = blockIdx.z;
    bool is_shared = (z >= BB * EE);
    int b, e = 0;
    if (is_shared) b = z - BB * EE;
    else {
        b = z >> 2; e = z & 3;
        if (g_gate[z] == 0.f) return;
    }
    int p0 = blockIdx.x * 128, o0 = blockIdx.y * 128;
    const int NITER = is_shared ? (CC / 32) : (KTOT / 32);   // 8 or 72

    // -------- load-stage addressing (per thread: half a row of A and B) -------
    int row = tid >> 1, half = tid & 1;
    int p = p0 + row;
    int ppad = ((p >> 5) + 1) * PADW + (p & 31) + 1;
    const float* aSrcBase = g_xT + (size_t)b * PADPX * CC + (size_t)ppad * CC + half * 16;
    const float* bSrcBase = is_shared
        ? g_swT + ((size_t)(o0 + row) << 8) + half * 16
        : g_wT + ((size_t)e * 9 * OO + (o0 + row)) * CC + half * 16;
    unsigned xr_row = (unsigned)(row & 7) << 4;
    unsigned aDstRow = sb + row * 128;
    unsigned hb = half * 64;

    auto load_stage = [&](int iter, int buf) {
        int c0, droff;
        long long boff;
        if (is_shared) { c0 = iter << 5; droff = 0; boff = c0; }
        else {
            int rs = iter >> 3; c0 = (iter & 7) << 5;
            droff = (rs / 3 - 1) * PADW + (rs % 3 - 1);
            boff = (long long)rs * OO * CC + c0;
        }
        const float* as = aSrcBase + (long long)droff * CC + c0;
        const float* bs = bSrcBase + boff;
        unsigned aDst = aDstRow + buf * STAGE_BYTES;
        unsigned bDst = aDst + TILE_BYTES;
        #pragma unroll
        for (int j = 0; j < 4; j++) {
            unsigned so = (hb + j * 16) ^ xr_row;
            cp16(aDst + so, as + j * 4);
            cp16(bDst + so, bs + j * 4);
        }
        cp_commit();
    };

    // -------- fragment addressing --------
    unsigned xr = (unsigned)g << 4;
    unsigned aOffW = (unsigned)(warp_m * 64 + g) * 128;
    unsigned bOffW = (unsigned)TILE_BYTES + (unsigned)(warp_n * 32 + g) * 128;

    float acc[4][4][4] = {};

    auto compute = [&](int buf) {
        const char* sm = smem + buf * STAGE_BYTES;
        #pragma unroll
        for (int kstep = 0; kstep < 4; kstep++) {
            unsigned kb = ((unsigned)(kstep * 32 + q * 8)) ^ xr;
            float2 alo[4], ahi[4];
            #pragma unroll
            for (int mi = 0; mi < 4; mi++) {
                alo[mi] = *(const float2*)(sm + aOffW + mi * 2048 + kb);
                ahi[mi] = *(const float2*)(sm + aOffW + mi * 2048 + 1024 + kb);
            }
            float2 bv[4];
            #pragma unroll
            for (int ni = 0; ni < 4; ni++)
                bv[ni] = *(const float2*)(sm + bOffW + ni * 1024 + kb);
            #pragma unroll
            for (int mi = 0; mi < 4; mi++) {
                unsigned a0 = __float_as_uint(alo[mi].x), a1 = __float_as_uint(ahi[mi].x);
                unsigned a2 = __float_as_uint(alo[mi].y), a3 = __float_as_uint(ahi[mi].y);
                #pragma unroll
                for (int ni = 0; ni < 4; ni++)
                    mma_tf32(acc[mi][ni],
                             a0, a1, a2, a3,
                             __float_as_uint(bv[ni].x), __float_as_uint(bv[ni].y));
            }
        }
    };

    // -------- pipeline --------
    #pragma unroll
    for (int s = 0; s < NSTG - 1; s++) load_stage(s, s);

    for (int i = 0; i < NITER; i++) {
        int pre = i + NSTG - 1;
        if (pre < NITER) load_stage(pre, pre % NSTG);
        int rem = NITER - 1 - i;
        if (rem >= 2)      asm volatile("cp.async.wait_group 2;" ::: "memory");
        else if (rem == 1) asm volatile("cp.async.wait_group 1;" ::: "memory");
        else               asm volatile("cp.async.wait_group 0;" ::: "memory");
        __syncthreads();
        compute(i % NSTG);
        __syncthreads();
    }

    // -------- epilogue: transpose through smem, coalesced [o][px] stores ------
    float* T = (float*)smem;                      // stride 132 floats per o-row
    #pragma unroll
    for (int mi = 0; mi < 4; mi++) {
        int m = warp_m * 64 + mi * 16 + g;
        #pragma unroll
        for (int ni = 0; ni < 4; ni++) {
            int n = warp_n * 32 + ni * 8 + 2 * q;
            T[n * 132 + m]           = acc[mi][ni][0];
            T[(n + 1) * 132 + m]     = acc[mi][ni][1];
            T[n * 132 + m + 8]       = acc[mi][ni][2];
            T[(n + 1) * 132 + m + 8] = acc[mi][ni][3];
        }
    }
    __syncthreads();

    float* outp = is_shared ? g_shared_raw + (size_t)b * OO * HWSZ
                            : g_expert_raw + (size_t)z * OO * HWSZ;
    {
        int r = tid >> 1, hp = tid & 1;
        const float4* srcv = (const float4*)(T + r * 132 + hp * 64);
        float4* dstv = (float4*)(outp + (size_t)(o0 + r) * HWSZ + p0 + hp * 64);
        #pragma unroll
        for (int j = 0; j < 16; j++) dstv[j] = srcv[j];
    }
}

// ---------------- K4: GroupNorm statistics ------------------------------------
__global__ void stats_kernel() {
    int bid = blockIdx.x;
    const float* src;
    float *mout, *rout;
    int idx;
    if (bid < BB * GG) {
        int b = bid / GG, g = bid % GG;
        src = g_shared_raw + ((size_t)b * OO + g * CPG) * HWSZ;
        mout = g_sh_mean; rout = g_sh_rstd; idx = bid;
    } else {
        int t = bid - BB * GG;
        int beg = t / GG;
        int g = t % GG;
        if (g_gate[beg] == 0.f) return;
        src = g_expert_raw + ((size_t)beg * OO + g * CPG) * HWSZ;
        mout = g_ex_mean; rout = g_ex_rstd; idx = t;
    }
    float s = 0.f, sq = 0.f;
    for (int i = threadIdx.x; i < CPG * HWSZ; i += 256) {
        float v = src[i];
        s += v;
        sq = fmaf(v, v, sq);
    }
    s = warpsum(s); sq = warpsum(sq);
    __shared__ float ss[8], sqs[8];
    int warp = threadIdx.x >> 5, lane = threadIdx.x & 31;
    if (lane == 0) { ss[warp] = s; sqs[warp] = sq; }
    __syncthreads();
    if (threadIdx.x == 0) {
        float S = 0.f, Q = 0.f;
        #pragma unroll
        for (int i = 0; i < 8; i++) { S += ss[i]; Q += sqs[i]; }
        const float inv = 1.0f / (CPG * HWSZ);
        float mean = S * inv;
        float var = Q * inv - mean * mean;
        mout[idx] = mean;
        rout[idx] = rsqrtf(var + EPSV);
    }
}

// ---------------- K5: normalize + SiLU + gated combine ------------------------
__global__ void combine_kernel(const float* __restrict__ egam, const float* __restrict__ ebet,
                               const float* __restrict__ sgam, const float* __restrict__ sbet,
                               float* __restrict__ out) {
    size_t i = (size_t)blockIdx.x * 256 + threadIdx.x;
    int hw = (int)(i & 1023);
    size_t t = i >> 10;
    int o = (int)(t & 255);
    int b = (int)(t >> 8);
    int g = o >> 5;

    float v = g_shared_raw[i];
    float m = g_sh_mean[b * GG + g], r = g_sh_rstd[b * GG + g];
    float vn = fmaf((v - m) * r, sgam[o], sbet[o]);
    float res = silu(vn);

    #pragma unroll
    for (int e = 0; e < EE; e++) {
        float ge = g_gate[b * EE + e];
        if (ge != 0.f) {
            int beg = b * EE + e;
            size_t ei = (((size_t)beg * OO + o) << 10) + hw;
            float ev = g_expert_raw[ei];
            float em = g_ex_mean[beg * GG + g], er = g_ex_rstd[beg * GG + g];
            float en = fmaf((ev - em) * er, egam[e * OO + o], ebet[e * OO + o]);
            res = fmaf(ge, silu(en), res);
        }
    }
    out[i] = res;
}

// ---------------- launch ------------------------------------------------------
extern "C" void kernel_launch(void* const* d_in, const int* in_sizes, int n_in,
                              void* d_out, int out_size) {
    const float* x    = (const float*)d_in[0];
    const float* rw1  = (const float*)d_in[1];
    const float* rb1  = (const float*)d_in[2];
    const float* rw2  = (const float*)d_in[3];
    const float* rb2  = (const float*)d_in[4];
    const float* ew   = (const float*)d_in[5];
    const float* egam = (const float*)d_in[6];
    const float* ebet = (const float*)d_in[7];
    const float* sw   = (const float*)d_in[8];
    const float* sgam = (const float*)d_in[9];
    const float* sbet = (const float*)d_in[10];
    float* out = (float*)d_out;

    cudaFuncSetAttribute(gemm_kernel, cudaFuncAttributeMaxDynamicSharedMemorySize, SMEM_TOTAL);

    pool_kernel<<<BB * CC / 8, 256>>>(x);
    router_kernel<<<1, 256>>>(rw1, rb1, rw2, rb2);
    xt_kernel<<<dim3(PADW, BB), 256>>>(x);
    wrepack_kernel<<<EE * OO * CC / 256, 256>>>(ew);
    swt_kernel<<<OO * CC / 256, 256>>>(sw);
    gemm_kernel<<<dim3(8, 2, BB * EE + BB), 256, SMEM_TOTAL>>>();
    stats_kernel<<<BB * GG + BB * EE * GG, 256>>>();
    combine_kernel<<<(BB * OO * HWSZ) / 256, 256>>>(egam, ebet, sgam, sbet, out);
}

// round 6
// speedup vs baseline: 2.8094x; 1.0390x over previous
#include <cuda_runtime.h>
#include <math.h>

// Problem constants
#define BB   16
#define CC   256
#define OO   256
#define HH   32
#define WW   32
#define EE   4
#define CR   16
#define GG   8
#define CPG  32
#define HWSZ 1024
#define EPSV 1e-5f

#define PADW 34
#define PADPX (PADW * PADW)
#define KTOT (CC * 9)              // 2304
#define NSTG 3
#define TILE_BYTES 16384           // 128 rows x 32 floats
#define STAGE_BYTES (2 * TILE_BYTES)
#define SMEM_TOTAL (NSTG * STAGE_BYTES)   // 98304

// ---------------- scratch ----------------------------------------------------
__device__ float g_pooled[BB * CC];
__device__ float g_gate[BB * EE];
__device__ float g_xT[(size_t)BB * PADPX * CC];              // padded px-major, k-permuted, tf32
__device__ float g_wT[(size_t)EE * 9 * OO * CC];             // [e][rs][o][c_perm], tf32
__device__ float g_swT[OO * CC];                             // shared 1x1 weights, permuted tf32
__device__ float g_shared_raw[(size_t)BB * OO * HWSZ];
__device__ float g_expert_raw[(size_t)BB * EE * OO * HWSZ];
__device__ float g_sh_mean[BB * GG], g_sh_rstd[BB * GG];
__device__ float g_ex_mean[BB * EE * GG], g_ex_rstd[BB * EE * GG];

// ---------------- helpers ----------------------------------------------------
__device__ __forceinline__ float warpsum(float v) {
    #pragma unroll
    for (int o = 16; o > 0; o >>= 1) v += __shfl_down_sync(0xffffffffu, v, o);
    return v;
}
__device__ __forceinline__ float silu(float v) { return v / (1.0f + expf(-v)); }

__device__ __forceinline__ float to_tf32(float x) {
    unsigned r;
    asm("cvt.rna.tf32.f32 %0, %1;" : "=r"(r) : "f"(x));
    return __uint_as_float(r);
}
// permute k within 8-groups so fragment pairs (k, k+4) are adjacent
__device__ __forceinline__ int kperm(int c) {
    return (c & ~7) | ((c & 3) << 1) | ((c & 4) >> 2);
}

__device__ __forceinline__ unsigned smem_u32(const void* p) {
    unsigned a;
    asm("{ .reg .u64 t; cvta.to.shared.u64 t, %1; cvt.u32.u64 %0, t; }" : "=r"(a) : "l"(p));
    return a;
}
__device__ __forceinline__ void cp16(unsigned dst, const float* src) {
    asm volatile("cp.async.cg.shared.global [%0], [%1], 16;" :: "r"(dst), "l"(src));
}
__device__ __forceinline__ void cp_commit() { asm volatile("cp.async.commit_group;"); }

__device__ __forceinline__ void mma_tf32(float* c, unsigned a0, unsigned a1, unsigned a2, unsigned a3,
                                         unsigned b0, unsigned b1) {
    asm volatile(
        "mma.sync.aligned.m16n8k8.row.col.f32.tf32.tf32.f32 "
        "{%0,%1,%2,%3}, {%4,%5,%6,%7}, {%8,%9}, {%0,%1,%2,%3};"
        : "+f"(c[0]), "+f"(c[1]), "+f"(c[2]), "+f"(c[3])
        : "r"(a0), "r"(a1), "r"(a2), "r"(a3), "r"(b0), "r"(b1));
}

// ---------------- K1a: global average pool -----------------------------------
__global__ void pool_kernel(const float* __restrict__ x) {
    int warp = threadIdx.x >> 5, lane = threadIdx.x & 31;
    int idx = blockIdx.x * 8 + warp;
    const float* p = x + (size_t)idx * HWSZ;
    float s = 0.f;
    for (int i = lane; i < HWSZ; i += 32) s += p[i];
    s = warpsum(s);
    if (lane == 0) g_pooled[idx] = s * (1.0f / HWSZ);
}

// ---------------- K1b: router ------------------------------------------------
__global__ void router_kernel(const float* __restrict__ w1, const float* __restrict__ b1,
                              const float* __restrict__ w2, const float* __restrict__ b2) {
    __shared__ float hs[BB][CR];
    __shared__ float lg[BB][EE];
    int tid = threadIdx.x;
    {
        int b = tid / CR, j = tid % CR;
        float s = b1[j];
        const float* wr = w1 + j * CC;
        const float* pr = g_pooled + b * CC;
        for (int c = 0; c < CC; c++) s = fmaf(wr[c], pr[c], s);
        hs[b][j] = silu(s);
    }
    __syncthreads();
    if (tid < BB * EE) {
        int b = tid / EE, e = tid % EE;
        float s = b2[e];
        for (int j = 0; j < CR; j++) s = fmaf(w2[e * CR + j], hs[b][j], s);
        lg[b][e] = s;
    }
    __syncthreads();
    if (tid < BB) {
        int b = tid;
        float m = lg[b][0];
        for (int e = 1; e < EE; e++) m = fmaxf(m, lg[b][e]);
        float p[EE]; float Z = 0.f;
        for (int e = 0; e < EE; e++) { p[e] = expf(lg[b][e] - m); Z += p[e]; }
        for (int e = 0; e < EE; e++) p[e] /= Z;
        int i1 = 0;
        for (int e = 1; e < EE; e++) if (p[e] > p[i1]) i1 = e;
        int i2 = -1;
        for (int e = 0; e < EE; e++) {
            if (e == i1) continue;
            if (i2 < 0 || p[e] > p[i2]) i2 = e;
        }
        float v1 = p[i1], v2 = p[i2], sum = v1 + v2;
        float wA = v1 / sum, wB = v2 / sum;
        if (wA < 0.01f) wA = 0.f;
        if (wB < 0.01f) wB = 0.f;
        for (int e = 0; e < EE; e++) g_gate[b * EE + e] = 0.f;
        g_gate[b * EE + i1] = wA;
        g_gate[b * EE + i2] = wB;
    }
}

// ---------------- K2: fused prep (xt + wrepack + swt) -------------------------
// blocks [0,544): x transpose; [544,1568): expert weight repack; [1568,1824): shared w
__global__ void prep_kernel(const float* __restrict__ x, const float* __restrict__ ew,
                            const float* __restrict__ sw) {
    int bid = blockIdx.x;
    int tid = threadIdx.x;
    if (bid < 544) {
        int b = bid / 34;
        int hp = bid % 34;
        int h = hp - 1;
        float* outrow = g_xT + ((size_t)b * PADPX + (size_t)hp * PADW) * CC;
        if (h < 0 || h >= HH) {
            for (int i = tid; i < PADW * CC; i += 256) outrow[i] = 0.f;
            return;
        }
        outrow[tid] = 0.f;
        outrow[33 * CC + tid] = 0.f;
        __shared__ float s[CC][33];
        for (int i = tid; i < CC * WW; i += 256) {
            int c = i >> 5, w = i & 31;
            s[c][w] = x[((size_t)(b * CC + c)) * HWSZ + h * WW + w];
        }
        __syncthreads();
        for (int i = tid; i < WW * CC; i += 256) {
            int w = i >> 8, c = i & 255;
            outrow[(size_t)(w + 1) * CC + kperm(c)] = to_tf32(s[c][w]);
        }
    } else if (bid < 1568) {
        int idx = (bid - 544) * 256 + tid;          // e*65536 + o*256 + c
        int c = idx & 255, o = (idx >> 8) & 255, e = idx >> 16;
        const float* src = ew + (size_t)idx * 9;
        int cp = kperm(c);
        #pragma unroll
        for (int j = 0; j < 9; j++)
            g_wT[(((size_t)(e * 9 + j) * OO + o) << 8) + cp] = to_tf32(src[j]);
    } else {
        int idx = (bid - 1568) * 256 + tid;         // o*256 + c
        int c = idx & 255, o = idx >> 8;
        g_swT[(o << 8) + kperm(c)] = to_tf32(sw[idx]);
    }
}

// ---------------- K3: unified tf32 warp-MMA GEMM ------------------------------
// grid (8 px-tiles, 2 o-tiles, 80); 256 threads.
// CTA tile 128px x 128o; warp grid 2(M) x 4(N); warp tile 64x32 (m16n8k8).
__global__ void __launch_bounds__(256, 2)
gemm_kernel() {
    extern __shared__ char smem[];
    unsigned sb = smem_u32(smem);
    int tid = threadIdx.x, warp = tid >> 5, lane = tid & 31;
    int warp_m = warp >> 2, warp_n = warp & 3;
    int g = lane >> 2, q = lane & 3;

    int z = blockIdx.z;
    bool is_shared = (z >= BB * EE);
    int b, e = 0;
    if (is_shared) b = z - BB * EE;
    else {
        b = z >> 2; e = z & 3;
        if (g_gate[z] == 0.f) return;
    }
    int p0 = blockIdx.x * 128, o0 = blockIdx.y * 128;
    const int NITER = is_shared ? (CC / 32) : (KTOT / 32);   // 8 or 72

    // -------- load-stage addressing (per thread: half a row of A and B) -------
    int row = tid >> 1, half = tid & 1;
    int p = p0 + row;
    int ppad = ((p >> 5) + 1) * PADW + (p & 31) + 1;
    const float* aSrcBase = g_xT + (size_t)b * PADPX * CC + (size_t)ppad * CC + half * 16;
    const float* bSrcBase = is_shared
        ? g_swT + ((size_t)(o0 + row) << 8) + half * 16
        : g_wT + ((size_t)e * 9 * OO + (o0 + row)) * CC + half * 16;
    unsigned xr_row = (unsigned)(row & 7) << 4;
    unsigned aDstRow = sb + row * 128;
    unsigned hb = half * 64;

    auto load_stage = [&](int iter, int buf) {
        int c0, droff;
        long long boff;
        if (is_shared) { c0 = iter << 5; droff = 0; boff = c0; }
        else {
            int rs = iter >> 3; c0 = (iter & 7) << 5;
            droff = (rs / 3 - 1) * PADW + (rs % 3 - 1);
            boff = (long long)rs * OO * CC + c0;
        }
        const float* as = aSrcBase + (long long)droff * CC + c0;
        const float* bs = bSrcBase + boff;
        unsigned aDst = aDstRow + buf * STAGE_BYTES;
        unsigned bDst = aDst + TILE_BYTES;
        #pragma unroll
        for (int j = 0; j < 4; j++) {
            unsigned so = (hb + j * 16) ^ xr_row;
            cp16(aDst + so, as + j * 4);
            cp16(bDst + so, bs + j * 4);
        }
        cp_commit();
    };

    // -------- fragment addressing --------
    unsigned xr = (unsigned)g << 4;
    unsigned aOffW = (unsigned)(warp_m * 64 + g) * 128;
    unsigned bOffW = (unsigned)TILE_BYTES + (unsigned)(warp_n * 32 + g) * 128;

    float acc[4][4][4] = {};

    auto compute = [&](int buf) {
        const char* sm = smem + buf * STAGE_BYTES;
        #pragma unroll
        for (int kstep = 0; kstep < 4; kstep++) {
            unsigned kb = ((unsigned)(kstep * 32 + q * 8)) ^ xr;
            float2 alo[4], ahi[4];
            #pragma unroll
            for (int mi = 0; mi < 4; mi++) {
                alo[mi] = *(const float2*)(sm + aOffW + mi * 2048 + kb);
                ahi[mi] = *(const float2*)(sm + aOffW + mi * 2048 + 1024 + kb);
            }
            float2 bv[4];
            #pragma unroll
            for (int ni = 0; ni < 4; ni++)
                bv[ni] = *(const float2*)(sm + bOffW + ni * 1024 + kb);
            #pragma unroll
            for (int mi = 0; mi < 4; mi++) {
                unsigned a0 = __float_as_uint(alo[mi].x), a1 = __float_as_uint(ahi[mi].x);
                unsigned a2 = __float_as_uint(alo[mi].y), a3 = __float_as_uint(ahi[mi].y);
                #pragma unroll
                for (int ni = 0; ni < 4; ni++)
                    mma_tf32(acc[mi][ni],
                             a0, a1, a2, a3,
                             __float_as_uint(bv[ni].x), __float_as_uint(bv[ni].y));
            }
        }
    };

    // -------- pipeline: ONE barrier per iteration ----------------------------
    #pragma unroll
    for (int s = 0; s < NSTG - 1; s++) load_stage(s, s);

    for (int i = 0; i < NITER; i++) {
        if (i < NITER - 1) asm volatile("cp.async.wait_group 1;" ::: "memory");
        else               asm volatile("cp.async.wait_group 0;" ::: "memory");
        __syncthreads();
        // buffer (i+2)%3 == (i-1)%3: all warps finished computing it at this barrier
        if (i + 2 < NITER) load_stage(i + 2, (i + 2) % 3);
        compute(i % 3);
    }
    __syncthreads();   // all compute done before smem is reused as transpose buffer

    // -------- epilogue: transpose through smem, coalesced [o][px] stores ------
    float* T = (float*)smem;                      // stride 132 floats per o-row
    #pragma unroll
    for (int mi = 0; mi < 4; mi++) {
        int m = warp_m * 64 + mi * 16 + g;
        #pragma unroll
        for (int ni = 0; ni < 4; ni++) {
            int n = warp_n * 32 + ni * 8 + 2 * q;
            T[n * 132 + m]           = acc[mi][ni][0];
            T[(n + 1) * 132 + m]     = acc[mi][ni][1];
            T[n * 132 + m + 8]       = acc[mi][ni][2];
            T[(n + 1) * 132 + m + 8] = acc[mi][ni][3];
        }
    }
    __syncthreads();

    float* outp = is_shared ? g_shared_raw + (size_t)b * OO * HWSZ
                            : g_expert_raw + (size_t)z * OO * HWSZ;
    {
        int r = tid >> 1, hp = tid & 1;
        const float4* srcv = (const float4*)(T + r * 132 + hp * 64);
        float4* dstv = (float4*)(outp + (size_t)(o0 + r) * HWSZ + p0 + hp * 64);
        #pragma unroll
        for (int j = 0; j < 16; j++) dstv[j] = srcv[j];
    }
}

// ---------------- K4: GroupNorm statistics ------------------------------------
__global__ void stats_kernel() {
    int bid = blockIdx.x;
    const float* src;
    float *mout, *rout;
    int idx;
    if (bid < BB * GG) {
        int b = bid / GG, g = bid % GG;
        src = g_shared_raw + ((size_t)b * OO + g * CPG) * HWSZ;
        mout = g_sh_mean; rout = g_sh_rstd; idx = bid;
    } else {
        int t = bid - BB * GG;
        int beg = t / GG;
        int g = t % GG;
        if (g_gate[beg] == 0.f) return;
        src = g_expert_raw + ((size_t)beg * OO + g * CPG) * HWSZ;
        mout = g_ex_mean; rout = g_ex_rstd; idx = t;
    }
    float s = 0.f, sq = 0.f;
    for (int i = threadIdx.x; i < CPG * HWSZ; i += 256) {
        float v = src[i];
        s += v;
        sq = fmaf(v, v, sq);
    }
    s = warpsum(s); sq = warpsum(sq);
    __shared__ float ss[8], sqs[8];
    int warp = threadIdx.x >> 5, lane = threadIdx.x & 31;
    if (lane == 0) { ss[warp] = s; sqs[warp] = sq; }
    __syncthreads();
    if (threadIdx.x == 0) {
        float S = 0.f, Q = 0.f;
        #pragma unroll
        for (int i = 0; i < 8; i++) { S += ss[i]; Q += sqs[i]; }
        const float inv = 1.0f / (CPG * HWSZ);
        float mean = S * inv;
        float var = Q * inv - mean * mean;
        mout[idx] = mean;
        rout[idx] = rsqrtf(var + EPSV);
    }
}

// ---------------- K5: normalize + SiLU + gated combine ------------------------
__global__ void combine_kernel(const float* __restrict__ egam, const float* __restrict__ ebet,
                               const float* __restrict__ sgam, const float* __restrict__ sbet,
                               float* __restrict__ out) {
    size_t i = (size_t)blockIdx.x * 256 + threadIdx.x;
    int hw = (int)(i & 1023);
    size_t t = i >> 10;
    int o = (int)(t & 255);
    int b = (int)(t >> 8);
    int g = o >> 5;

    float v = g_shared_raw[i];
    float m = g_sh_mean[b * GG + g], r = g_sh_rstd[b * GG + g];
    float vn = fmaf((v - m) * r, sgam[o], sbet[o]);
    float res = silu(vn);

    #pragma unroll
    for (int e = 0; e < EE; e++) {
        float ge = g_gate[b * EE + e];
        if (ge != 0.f) {
            int beg = b * EE + e;
            size_t ei = (((size_t)beg * OO + o) << 10) + hw;
            float ev = g_expert_raw[ei];
            float em = g_ex_mean[beg * GG + g], er = g_ex_rstd[beg * GG + g];
            float en = fmaf((ev - em) * er, egam[e * OO + o], ebet[e * OO + o]);
            res = fmaf(ge, silu(en), res);
        }
    }
    out[i] = res;
}

// ---------------- launch ------------------------------------------------------
extern "C" void kernel_launch(void* const* d_in, const int* in_sizes, int n_in,
                              void* d_out, int out_size) {
    const float* x    = (const float*)d_in[0];
    const float* rw1  = (const float*)d_in[1];
    const float* rb1  = (const float*)d_in[2];
    const float* rw2  = (const float*)d_in[3];
    const float* rb2  = (const float*)d_in[4];
    const float* ew   = (const float*)d_in[5];
    const float* egam = (const float*)d_in[6];
    const float* ebet = (const float*)d_in[7];
    const float* sw   = (const float*)d_in[8];
    const float* sgam = (const float*)d_in[9];
    const float* sbet = (const float*)d_in[10];
    float* out = (float*)d_out;

    cudaFuncSetAttribute(gemm_kernel, cudaFuncAttributeMaxDynamicSharedMemorySize, SMEM_TOTAL);

    pool_kernel<<<BB * CC / 8, 256>>>(x);
    router_kernel<<<1, 256>>>(rw1, rb1, rw2, rb2);
    prep_kernel<<<1824, 256>>>(x, ew, sw);
    gemm_kernel<<<dim3(8, 2, BB * EE + BB), 256, SMEM_TOTAL>>>();
    stats_kernel<<<BB * GG + BB * EE * GG, 256>>>();
    combine_kernel<<<(BB * OO * HWSZ) / 256, 256>>>(egam, ebet, sgam, sbet, out);
}